// round 7
// baseline (speedup 1.0000x reference)
#include <cuda_runtime.h>
#include <cuda_bf16.h>
#include <cstdint>
#include <cstddef>

// y[32,11008] = x[32,4096] @ (Wq * scale)^T + bias
// R7: wavefront-minimal memory paths.
//  - W: coalesced LDG.128 (4 wf) -> STS.128 -> conflict-free swizzled LDS frags
//  - x: prep kernel writes hi/lo bf16 B-fragments in warp-contiguous order to
//       global scratch; each frag load = one 256B-contiguous warp LDG.64 (2 wf)
//  - ternary->bf16 via 4 ALU ops (no I2F); mma.sync m16n8k16 bf16.

#define OUTN 11008
#define INK  4096
#define TM   64
#define NCHUNK 64            // 64 k per chunk
#define NCTA (OUTN / TM)     // 172
#define NTHREADS 256

// frag-ordered x scratch: addr = ((c*4+s)*8 + f)*256 + lane*8, f = ng*4+nf
__device__ __align__(16) unsigned char g_xscr[64 * 8192];   // 512 KB

__device__ __forceinline__ uint32_t tern2bf(uint32_t w0, uint32_t w1) {
    uint32_t p = __byte_perm(w0, w1, 0x5410);
    uint32_t m = (p & 0x00010001u) * 0x3F80u;
    return m | (p & 0x80008000u);
}

__device__ __forceinline__ void mma16816(float d[4],
                                         uint32_t a0, uint32_t a1, uint32_t a2, uint32_t a3,
                                         uint32_t b0, uint32_t b1) {
    asm volatile(
        "mma.sync.aligned.m16n8k16.row.col.f32.bf16.bf16.f32 "
        "{%0,%1,%2,%3}, {%4,%5,%6,%7}, {%8,%9}, {%0,%1,%2,%3};\n"
        : "+f"(d[0]), "+f"(d[1]), "+f"(d[2]), "+f"(d[3])
        : "r"(a0), "r"(a1), "r"(a2), "r"(a3), "r"(b0), "r"(b1));
}

// ---------------- prep kernel: x -> hi/lo bf16 frag-ordered scratch ----------
__global__ void __launch_bounds__(256) prep_x(const float* __restrict__ X) {
    int t  = blockIdx.x * blockDim.x + threadIdx.x;   // 0..32767
    int b  = t >> 10;                                 // batch 0..31
    int k4 = t & 1023;                                // float4 idx in row
    float4 v = *reinterpret_cast<const float4*>(X + (size_t)b * INK + (size_t)k4 * 4);

    __nv_bfloat16 h0 = __float2bfloat16_rn(v.x);
    __nv_bfloat16 h1 = __float2bfloat16_rn(v.y);
    __nv_bfloat16 h2 = __float2bfloat16_rn(v.z);
    __nv_bfloat16 h3 = __float2bfloat16_rn(v.w);
    __nv_bfloat16 l0 = __float2bfloat16_rn(v.x - __bfloat162float(h0));
    __nv_bfloat16 l1 = __float2bfloat16_rn(v.y - __bfloat162float(h1));
    __nv_bfloat16 l2 = __float2bfloat16_rn(v.z - __bfloat162float(h2));
    __nv_bfloat16 l3 = __float2bfloat16_rn(v.w - __bfloat162float(h3));
    __nv_bfloat162 hp0; hp0.x = h0; hp0.y = h1;
    __nv_bfloat162 hp1; hp1.x = h2; hp1.y = h3;
    __nv_bfloat162 lp0; lp0.x = l0; lp0.y = l1;
    __nv_bfloat162 lp1; lp1.x = l2; lp1.y = l3;
    uint2 hv = make_uint2(*reinterpret_cast<uint32_t*>(&hp0), *reinterpret_cast<uint32_t*>(&hp1));
    uint2 lv = make_uint2(*reinterpret_cast<uint32_t*>(&lp0), *reinterpret_cast<uint32_t*>(&lp1));

    int c  = k4 >> 4;
    int s  = (k4 >> 2) & 3;
    int cc = k4 & 3;
    int ng  = b >> 4;
    int r16 = b & 15;
    int n_hi = ng * 32 + r16;        // scratch row for hi
    int n_lo = n_hi + 16;            // scratch row for lo
    {
        int f = n_hi >> 3, rr = n_hi & 7;
        size_t dst = ((size_t)(c * 4 + s) * 8 + f) * 256 + (size_t)(rr * 4 + cc) * 8;
        *reinterpret_cast<uint2*>(g_xscr + dst) = hv;
    }
    {
        int f = n_lo >> 3, rr = n_lo & 7;
        size_t dst = ((size_t)(c * 4 + s) * 8 + f) * 256 + (size_t)(rr * 4 + cc) * 8;
        *reinterpret_cast<uint2*>(g_xscr + dst) = lv;
    }
}

// ---------------- main GEMM kernel ------------------------------------------
__global__ void __launch_bounds__(NTHREADS, 2)
lin2b_main(const int* __restrict__ W, const float* __restrict__ SC,
           const float* __restrict__ BI, float* __restrict__ OUT)
{
    __shared__ __align__(16) unsigned char wsm[2][64 * 256];   // 32 KB

    int tid  = threadIdx.x;
    int wid  = tid >> 5;
    int lane = tid & 31;
    int mwid = wid & 3;
    int ng   = wid >> 2;
    int rr   = lane >> 2;
    int cc   = lane & 3;
    int row0 = blockIdx.x * TM;

    // --- coalesced W load mapping: warp covers rows wid*8..+7 ---
    int lrow = wid * 8 + (lane >> 4);        // + 2j per j
    int lcol = (lane & 15) * 16;
    const char* wsrc = reinterpret_cast<const char*>(W)
                       + (size_t)(row0 + lrow) * INK * 4 + lcol;
    // STS offset (row parity invariant under +2j): swizzle col by (row&1)<<6
    uint32_t sts_off = (uint32_t)(lrow * 256 + (lcol ^ ((lrow & 1) << 6)));

    // --- frag LDS mapping ---
    uint32_t lds_row = (uint32_t)((mwid * 16 + rr) * 256);
    uint32_t lds_x   = (uint32_t)((rr & 1) << 6);

    // --- B frag base ---
    const char* xbase = reinterpret_cast<const char*>(g_xscr)
                        + (size_t)(ng * 4) * 256 + (size_t)lane * 8;

    float acc[4][4];
#pragma unroll
    for (int i = 0; i < 4; ++i)
#pragma unroll
        for (int j = 0; j < 4; ++j) acc[i][j] = 0.0f;

    uint4 wr[2][4];

    // prologue: chunk0 -> wr[0], chunk1 -> wr[1]; STS chunk0
#pragma unroll
    for (int j = 0; j < 4; ++j)
        wr[0][j] = *reinterpret_cast<const uint4*>(wsrc + (size_t)(2 * j) * INK * 4);
#pragma unroll
    for (int j = 0; j < 4; ++j)
        wr[1][j] = *reinterpret_cast<const uint4*>(wsrc + (size_t)(2 * j) * INK * 4 + 256);
#pragma unroll
    for (int j = 0; j < 4; ++j)
        *reinterpret_cast<uint4*>(wsm[0] + sts_off + j * 512) = wr[0][j];
    __syncthreads();

#pragma unroll 1
    for (int c = 0; c < NCHUNK; ++c) {
        // prefetch W chunk c+2 into the reg slot freed by chunk c
        if (c + 2 < NCHUNK) {
#pragma unroll
            for (int j = 0; j < 4; ++j)
                wr[c & 1][j] = *reinterpret_cast<const uint4*>(
                    wsrc + (size_t)(2 * j) * INK * 4 + (size_t)(c + 2) * 256);
        }
        // stage chunk c+1 from regs into the other smem buffer
        if (c + 1 < NCHUNK) {
#pragma unroll
            for (int j = 0; j < 4; ++j)
                *reinterpret_cast<uint4*>(wsm[(c + 1) & 1] + sts_off + j * 512) =
                    wr[(c + 1) & 1][j];
        }

        // B frags for chunk c (warp-contiguous 256B blocks; L1/L2 resident)
        uint2 bfr[4][4];
        const char* xc = xbase + (size_t)c * 8192;
#pragma unroll
        for (int s = 0; s < 4; ++s)
#pragma unroll
            for (int nf = 0; nf < 4; ++nf)
                bfr[s][nf] = *reinterpret_cast<const uint2*>(xc + s * 2048 + nf * 256);

        const unsigned char* wb = wsm[c & 1];
#pragma unroll
        for (int s = 0; s < 4; ++s) {
            uint32_t off = (uint32_t)((s * 64 + cc * 16) ^ lds_x);
            uint4 wa  = *reinterpret_cast<const uint4*>(wb + lds_row + off);
            uint4 wbb = *reinterpret_cast<const uint4*>(wb + lds_row + 2048 + off);
            uint32_t a0 = tern2bf(wa.x,  wa.y);
            uint32_t a2 = tern2bf(wa.z,  wa.w);
            uint32_t a1 = tern2bf(wbb.x, wbb.y);
            uint32_t a3 = tern2bf(wbb.z, wbb.w);
#pragma unroll
            for (int nf = 0; nf < 4; ++nf)
                mma16816(acc[nf], a0, a1, a2, a3, bfr[s][nf].x, bfr[s][nf].y);
        }
        __syncthreads();
    }

    // ---- epilogue: hi (nf 0..1) + lo (nf 2..3), scale + bias ----
    int o0 = row0 + mwid * 16 + rr;
    int o1 = o0 + 8;
    float s0 = SC[o0], bi0 = BI[o0];
    float s1 = SC[o1], bi1 = BI[o1];
#pragma unroll
    for (int i = 0; i < 2; ++i) {
        int b0 = ng * 16 + i * 8 + 2 * cc;
        int b1 = b0 + 1;
        float v00 = acc[i][0] + acc[i + 2][0];
        float v01 = acc[i][1] + acc[i + 2][1];
        float v10 = acc[i][2] + acc[i + 2][2];
        float v11 = acc[i][3] + acc[i + 2][3];
        OUT[(size_t)b0 * OUTN + o0] = fmaf(s0, v00, bi0);
        OUT[(size_t)b1 * OUTN + o0] = fmaf(s0, v01, bi0);
        OUT[(size_t)b0 * OUTN + o1] = fmaf(s1, v10, bi1);
        OUT[(size_t)b1 * OUTN + o1] = fmaf(s1, v11, bi1);
    }
}

extern "C" void kernel_launch(void* const* d_in, const int* in_sizes, int n_in,
                              void* d_out, int out_size) {
    (void)in_sizes; (void)n_in; (void)out_size;
    const float* x  = (const float*)d_in[0];
    const int*   wq = (const int*)d_in[1];
    const float* sc = (const float*)d_in[2];
    const float* bi = (const float*)d_in[3];
    float* out = (float*)d_out;

    prep_x<<<128, 256>>>(x);
    lin2b_main<<<NCTA, NTHREADS>>>(wq, sc, bi, out);
}

// round 10
// speedup vs baseline: 2.2852x; 2.2852x over previous
#include <cuda_runtime.h>
#include <cuda_bf16.h>
#include <cstdint>
#include <cstddef>

// y[32,11008] = x[32,4096] @ (Wq * scale)^T + bias
// R10 (= R9 with W double-buffer fixed to prefetch-distance-1, R2 cadence):
// W: LDG->regs->HMMA; x frags via smem (prep kernel hoists hi/lo bf16 split);
// split-K x4 (344 CTAs, 2/SM); ALU-only ternary->bf16; deterministic reduce.

#define OUTN 11008
#define INK  4096
#define TM   128
#define NSPLIT 4
#define CHUNKS 16            // K-chunks per CTA (64 k each)
#define NCTA (OUTN / TM * NSPLIT)   // 344
#define NTHREADS 256
#define XROW 160             // x smem row stride (bytes)

__device__ __align__(16) __nv_bfloat16 g_x[64 * INK];          // hi rows 0-31, lo 32-63
__device__ __align__(16) float g_part[NSPLIT * 32 * OUTN];     // 5.6 MB partials

__device__ __forceinline__ uint32_t tern2bf(uint32_t w0, uint32_t w1) {
    uint32_t p = __byte_perm(w0, w1, 0x5410);
    uint32_t m = (p & 0x00010001u) * 0x3F80u;
    return m | (p & 0x80008000u);
}

__device__ __forceinline__ void mma16816(float d[4],
                                         uint32_t a0, uint32_t a1, uint32_t a2, uint32_t a3,
                                         uint32_t b0, uint32_t b1) {
    asm volatile(
        "mma.sync.aligned.m16n8k16.row.col.f32.bf16.bf16.f32 "
        "{%0,%1,%2,%3}, {%4,%5,%6,%7}, {%8,%9}, {%0,%1,%2,%3};\n"
        : "+f"(d[0]), "+f"(d[1]), "+f"(d[2]), "+f"(d[3])
        : "r"(a0), "r"(a1), "r"(a2), "r"(a3), "r"(b0), "r"(b1));
}

// ---------------- prep: x f32 -> hi/lo bf16 rows ----------------------------
__global__ void __launch_bounds__(256) prep_x(const float* __restrict__ X) {
    int t = blockIdx.x * blockDim.x + threadIdx.x;    // 0..32767
    int b = t >> 10;
    int k4 = (t & 1023) * 4;
    float4 v = *reinterpret_cast<const float4*>(X + (size_t)b * INK + k4);

    __nv_bfloat16 h0 = __float2bfloat16_rn(v.x);
    __nv_bfloat16 h1 = __float2bfloat16_rn(v.y);
    __nv_bfloat16 h2 = __float2bfloat16_rn(v.z);
    __nv_bfloat16 h3 = __float2bfloat16_rn(v.w);
    __nv_bfloat162 hp0; hp0.x = h0; hp0.y = h1;
    __nv_bfloat162 hp1; hp1.x = h2; hp1.y = h3;
    __nv_bfloat16 l0 = __float2bfloat16_rn(v.x - __bfloat162float(h0));
    __nv_bfloat16 l1 = __float2bfloat16_rn(v.y - __bfloat162float(h1));
    __nv_bfloat16 l2 = __float2bfloat16_rn(v.z - __bfloat162float(h2));
    __nv_bfloat16 l3 = __float2bfloat16_rn(v.w - __bfloat162float(h3));
    __nv_bfloat162 lp0; lp0.x = l0; lp0.y = l1;
    __nv_bfloat162 lp1; lp1.x = l2; lp1.y = l3;

    *reinterpret_cast<__nv_bfloat162*>(g_x + (size_t)b * INK + k4)            = hp0;
    *reinterpret_cast<__nv_bfloat162*>(g_x + (size_t)b * INK + k4 + 2)        = hp1;
    *reinterpret_cast<__nv_bfloat162*>(g_x + (size_t)(b + 32) * INK + k4)     = lp0;
    *reinterpret_cast<__nv_bfloat162*>(g_x + (size_t)(b + 32) * INK + k4 + 2) = lp1;
}

// ---------------- main GEMM (per-split partial) -----------------------------
__global__ void __launch_bounds__(NTHREADS, 2)
lin2b_main(const int* __restrict__ W)
{
    __shared__ __align__(16) unsigned char xsm[2][64 * XROW];   // 20 KB

    int tid  = threadIdx.x;
    int wid  = tid >> 5;
    int lane = tid & 31;
    int rr   = lane >> 2;
    int cc   = lane & 3;

    int mtile = blockIdx.x >> 2;
    int split = blockIdx.x & 3;
    int row0  = mtile * TM;
    int kb    = split * CHUNKS;       // first chunk index (64k units)

    // W frag pointers: rows (wid*16+rr) and +8, cols 4*cc within each chunk
    const int* wp0 = W + (size_t)(row0 + wid * 16 + rr) * INK + (size_t)kb * 64 + 4 * cc;
    const int* wp1 = wp0 + (size_t)8 * INK;

    // x stage mapping: thread t covers hi row (t>>3) and lo row (t>>3)+32
    int xr   = tid >> 3;
    int xc16 = tid & 7;
    const __nv_bfloat16* xsrc0 = g_x + (size_t)xr * INK + (size_t)kb * 64 + xc16 * 8;
    const __nv_bfloat16* xsrc1 = xsrc0 + (size_t)32 * INK;
    uint32_t xoff0 = (uint32_t)(xr * XROW + xc16 * 16);
    uint32_t xoff1 = xoff0 + 32 * XROW;

    float acc[8][4];
#pragma unroll
    for (int i = 0; i < 8; ++i)
#pragma unroll
        for (int j = 0; j < 4; ++j) acc[i][j] = 0.0f;

    uint4 w0[8], w1[8];

    // prologue: W chunk 0 -> w0; x chunk 0 -> smem buf 0
#pragma unroll
    for (int s = 0; s < 4; ++s) {
        w0[2*s]   = *reinterpret_cast<const uint4*>(wp0 + s * 16);
        w0[2*s+1] = *reinterpret_cast<const uint4*>(wp1 + s * 16);
    }
    *reinterpret_cast<uint4*>(&xsm[0][0] + xoff0) = *reinterpret_cast<const uint4*>(xsrc0);
    *reinterpret_cast<uint4*>(&xsm[0][0] + xoff1) = *reinterpret_cast<const uint4*>(xsrc1);
    __syncthreads();

#pragma unroll 1
    for (int c = 0; c < CHUNKS; ++c) {
        uint4* wcur = (c & 1) ? w1 : w0;   // holds chunk c
        uint4* wnxt = (c & 1) ? w0 : w1;   // free: chunk c-1 already consumed

        bool more = (c + 1) < CHUNKS;
        // prefetch W chunk c+1 into the free buffer (distance 1, R2 cadence)
        if (more) {
#pragma unroll
            for (int s = 0; s < 4; ++s) {
                wnxt[2*s]   = *reinterpret_cast<const uint4*>(wp0 + (c + 1) * 64 + s * 16);
                wnxt[2*s+1] = *reinterpret_cast<const uint4*>(wp1 + (c + 1) * 64 + s * 16);
            }
        }
        // x chunk c+1 -> regs
        uint4 xv0, xv1;
        if (more) {
            xv0 = *reinterpret_cast<const uint4*>(xsrc0 + (c + 1) * 64);
            xv1 = *reinterpret_cast<const uint4*>(xsrc1 + (c + 1) * 64);
        }

        const unsigned char* xb = &xsm[c & 1][0];
#pragma unroll
        for (int s = 0; s < 4; ++s) {
            uint4 wa = wcur[2*s];
            uint4 wb = wcur[2*s+1];
            uint32_t a0 = tern2bf(wa.x, wa.y);
            uint32_t a2 = tern2bf(wa.z, wa.w);
            uint32_t a1 = tern2bf(wb.x, wb.y);
            uint32_t a3 = tern2bf(wb.z, wb.w);
#pragma unroll
            for (int nf = 0; nf < 8; ++nf) {
                uint2 bv = *reinterpret_cast<const uint2*>(
                    xb + (nf * 8 + rr) * XROW + s * 32 + cc * 8);
                mma16816(acc[nf], a0, a1, a2, a3, bv.x, bv.y);
            }
        }

        if (more) {
            unsigned char* xn = &xsm[(c + 1) & 1][0];
            *reinterpret_cast<uint4*>(xn + xoff0) = xv0;
            *reinterpret_cast<uint4*>(xn + xoff1) = xv1;
        }
        __syncthreads();
    }

    // ---- partial epilogue: hi + lo, no scale/bias yet ----
    int o0 = row0 + wid * 16 + rr;
    int o1 = o0 + 8;
    float* pb = g_part + (size_t)split * 32 * OUTN;
#pragma unroll
    for (int nf = 0; nf < 4; ++nf) {
        int b0 = nf * 8 + 2 * cc;
        int b1 = b0 + 1;
        pb[(size_t)b0 * OUTN + o0] = acc[nf][0] + acc[nf + 4][0];
        pb[(size_t)b1 * OUTN + o0] = acc[nf][1] + acc[nf + 4][1];
        pb[(size_t)b0 * OUTN + o1] = acc[nf][2] + acc[nf + 4][2];
        pb[(size_t)b1 * OUTN + o1] = acc[nf][3] + acc[nf + 4][3];
    }
}

// ---------------- reduce: out = bias + scale * sum(parts) -------------------
__global__ void __launch_bounds__(256)
reduce_k(const float* __restrict__ SC, const float* __restrict__ BI,
         float* __restrict__ OUT)
{
    int idx = blockIdx.x * blockDim.x + threadIdx.x;
    if (idx >= 32 * OUTN) return;
    int o = idx % OUTN;
    float s = g_part[idx];
#pragma unroll
    for (int sp = 1; sp < NSPLIT; ++sp)
        s += g_part[(size_t)sp * 32 * OUTN + idx];
    OUT[idx] = fmaf(SC[o], s, BI[o]);
}

extern "C" void kernel_launch(void* const* d_in, const int* in_sizes, int n_in,
                              void* d_out, int out_size) {
    (void)in_sizes; (void)n_in; (void)out_size;
    const float* x  = (const float*)d_in[0];
    const int*   wq = (const int*)d_in[1];
    const float* sc = (const float*)d_in[2];
    const float* bi = (const float*)d_in[3];
    float* out = (float*)d_out;

    prep_x<<<128, 256>>>(x);
    lin2b_main<<<NCTA, NTHREADS>>>(wq);
    reduce_k<<<(32 * OUTN + 255) / 256, 256>>>(sc, bi, out);
}

// round 11
// speedup vs baseline: 3.3833x; 1.4805x over previous
#include <cuda_runtime.h>
#include <cuda_fp16.h>
#include <cstdint>
#include <cstddef>

// y[32,11008] = x[32,4096] @ (Wq * scale)^T + bias
// R11: R10 + (a) NSPLIT 4->8 to cut wave quantization (1.72x -> 1.29x),
// (b) single-path fp16 x (drops hi/lo split; halves HMMA/LDS/smem).
// W: LDG.128 -> ALU ternary->fp16 -> HMMA. Deterministic split reduce.

#define OUTN 11008
#define INK  4096
#define TM   128
#define NSPLIT 8
#define CHUNKS 8             // K-chunks per CTA (64 k each)
#define NCTA (OUTN / TM * NSPLIT)   // 688
#define NTHREADS 256
#define XROW 160             // x smem row stride (bytes): 128 data + 32 pad

__device__ __align__(16) __half g_x[32 * INK];                 // fp16 x
__device__ __align__(16) float g_part[NSPLIT * 32 * OUTN];     // 11.3 MB partials

// ternary int32 pair -> packed fp16x2 {0,+-1.0}; 4 lat-4 ALU ops.
__device__ __forceinline__ uint32_t tern2h(uint32_t w0, uint32_t w1) {
    uint32_t p = __byte_perm(w0, w1, 0x5410);   // low 16 bits of each int
    uint32_t m = (p & 0x00010001u) * 0x3C00u;   // +-1.0 magnitude (fp16)
    return m | (p & 0x80008000u);               // sign
}

__device__ __forceinline__ void mma16816(float d[4],
                                         uint32_t a0, uint32_t a1, uint32_t a2, uint32_t a3,
                                         uint32_t b0, uint32_t b1) {
    asm volatile(
        "mma.sync.aligned.m16n8k16.row.col.f32.f16.f16.f32 "
        "{%0,%1,%2,%3}, {%4,%5,%6,%7}, {%8,%9}, {%0,%1,%2,%3};\n"
        : "+f"(d[0]), "+f"(d[1]), "+f"(d[2]), "+f"(d[3])
        : "r"(a0), "r"(a1), "r"(a2), "r"(a3), "r"(b0), "r"(b1));
}

// ---------------- prep: x f32 -> fp16 ----------------------------------------
__global__ void __launch_bounds__(256) prep_x(const float* __restrict__ X) {
    int t = blockIdx.x * blockDim.x + threadIdx.x;    // 0..32767
    int b = t >> 10;
    int k4 = (t & 1023) * 4;
    float4 v = *reinterpret_cast<const float4*>(X + (size_t)b * INK + k4);
    __half2 p0 = __floats2half2_rn(v.x, v.y);
    __half2 p1 = __floats2half2_rn(v.z, v.w);
    uint2 pk = make_uint2(*reinterpret_cast<uint32_t*>(&p0),
                          *reinterpret_cast<uint32_t*>(&p1));
    *reinterpret_cast<uint2*>(g_x + (size_t)b * INK + k4) = pk;
}

// ---------------- main GEMM (per-split partial) ------------------------------
__global__ void __launch_bounds__(NTHREADS, 2)
lin2b_main(const int* __restrict__ W)
{
    __shared__ __align__(16) unsigned char xsm[2][32 * XROW];   // 10 KB

    int tid  = threadIdx.x;
    int wid  = tid >> 5;
    int lane = tid & 31;
    int rr   = lane >> 2;
    int cc   = lane & 3;

    int mtile = blockIdx.x >> 3;
    int split = blockIdx.x & 7;
    int row0  = mtile * TM;
    int kb    = split * CHUNKS;       // first chunk index (64k units)

    // W frag pointers: rows (wid*16+rr) and +8, cols 4*cc within each chunk
    const int* wp0 = W + (size_t)(row0 + wid * 16 + rr) * INK + (size_t)kb * 64 + 4 * cc;
    const int* wp1 = wp0 + (size_t)8 * INK;

    // x stage mapping: thread t covers row (t>>3), 16B col t&7
    int xr   = tid >> 3;              // 0..31
    int xc16 = tid & 7;
    const __half* xsrc = g_x + (size_t)xr * INK + (size_t)kb * 64 + xc16 * 8;
    uint32_t xoff = (uint32_t)(xr * XROW + xc16 * 16);

    float acc[4][4];
#pragma unroll
    for (int i = 0; i < 4; ++i)
#pragma unroll
        for (int j = 0; j < 4; ++j) acc[i][j] = 0.0f;

    uint4 w0[8], w1[8];

    // prologue: W chunk 0 -> w0; x chunk 0 -> smem buf 0
#pragma unroll
    for (int s = 0; s < 4; ++s) {
        w0[2*s]   = *reinterpret_cast<const uint4*>(wp0 + s * 16);
        w0[2*s+1] = *reinterpret_cast<const uint4*>(wp1 + s * 16);
    }
    *reinterpret_cast<uint4*>(&xsm[0][0] + xoff) = *reinterpret_cast<const uint4*>(xsrc);
    __syncthreads();

#pragma unroll 1
    for (int c = 0; c < CHUNKS; ++c) {
        uint4* wcur = (c & 1) ? w1 : w0;   // holds chunk c
        uint4* wnxt = (c & 1) ? w0 : w1;   // free (chunk c-1 consumed)

        bool more = (c + 1) < CHUNKS;
        if (more) {
#pragma unroll
            for (int s = 0; s < 4; ++s) {
                wnxt[2*s]   = *reinterpret_cast<const uint4*>(wp0 + (c + 1) * 64 + s * 16);
                wnxt[2*s+1] = *reinterpret_cast<const uint4*>(wp1 + (c + 1) * 64 + s * 16);
            }
        }
        uint4 xv;
        if (more) xv = *reinterpret_cast<const uint4*>(xsrc + (c + 1) * 64);

        const unsigned char* xb = &xsm[c & 1][0];
#pragma unroll
        for (int s = 0; s < 4; ++s) {
            uint4 wa = wcur[2*s];
            uint4 wb = wcur[2*s+1];
            uint32_t a0 = tern2h(wa.x, wa.y);
            uint32_t a2 = tern2h(wa.z, wa.w);
            uint32_t a1 = tern2h(wb.x, wb.y);
            uint32_t a3 = tern2h(wb.z, wb.w);
#pragma unroll
            for (int nf = 0; nf < 4; ++nf) {
                uint2 bv = *reinterpret_cast<const uint2*>(
                    xb + (nf * 8 + rr) * XROW + s * 32 + cc * 8);
                mma16816(acc[nf], a0, a1, a2, a3, bv.x, bv.y);
            }
        }

        if (more) {
            *reinterpret_cast<uint4*>(&xsm[(c + 1) & 1][0] + xoff) = xv;
        }
        __syncthreads();
    }

    // ---- partial epilogue (no scale/bias yet) ----
    int o0 = row0 + wid * 16 + rr;
    int o1 = o0 + 8;
    float* pb = g_part + (size_t)split * 32 * OUTN;
#pragma unroll
    for (int nf = 0; nf < 4; ++nf) {
        int b0 = nf * 8 + 2 * cc;
        int b1 = b0 + 1;
        pb[(size_t)b0 * OUTN + o0] = acc[nf][0];
        pb[(size_t)b1 * OUTN + o0] = acc[nf][1];
        pb[(size_t)b0 * OUTN + o1] = acc[nf][2];
        pb[(size_t)b1 * OUTN + o1] = acc[nf][3];
    }
}

// ---------------- reduce: out = bias + scale * sum(parts) --------------------
__global__ void __launch_bounds__(256)
reduce_k(const float* __restrict__ SC, const float* __restrict__ BI,
         float* __restrict__ OUT)
{
    int idx = blockIdx.x * blockDim.x + threadIdx.x;
    if (idx >= 32 * OUTN) return;
    int o = idx % OUTN;
    float s = g_part[idx];
#pragma unroll
    for (int sp = 1; sp < NSPLIT; ++sp)
        s += g_part[(size_t)sp * 32 * OUTN + idx];
    OUT[idx] = fmaf(SC[o], s, BI[o]);
}

extern "C" void kernel_launch(void* const* d_in, const int* in_sizes, int n_in,
                              void* d_out, int out_size) {
    (void)in_sizes; (void)n_in; (void)out_size;
    const float* x  = (const float*)d_in[0];
    const int*   wq = (const int*)d_in[1];
    const float* sc = (const float*)d_in[2];
    const float* bi = (const float*)d_in[3];
    float* out = (float*)d_out;

    prep_x<<<128, 256>>>(x);
    lin2b_main<<<NCTA, NTHREADS>>>(wq);
    reduce_k<<<(32 * OUTN + 255) / 256, 256>>>(sc, bi, out);
}

// round 12
// speedup vs baseline: 3.6745x; 1.0861x over previous
#include <cuda_runtime.h>
#include <cuda_fp16.h>
#include <cstdint>
#include <cstddef>

// y[32,11008] = x[32,4096] @ (Wq * scale)^T + bias
// R12: NSPLIT 8->16 (stretch 1.29->1.075); x converted once per CTA into
// read-only smem (prologue) -> NO barriers in main loop, prep kernel deleted.
// W: LDG.128 -> ALU ternary->fp16 -> HMMA m16n8k16. Deterministic reduce.

#define OUTN 11008
#define INK  4096
#define TM   128
#define NSPLIT 16
#define CHUNKS 4                    // K-chunks per CTA (64 k each), K=256/CTA
#define NCTA (OUTN / TM * NSPLIT)   // 1376
#define NTHREADS 256
#define XROW 544                    // x smem row stride bytes (136w = 8 mod 32)

__device__ __align__(16) float g_part[NSPLIT * 32 * OUTN];   // 22.5 MB partials

// ternary int32 pair -> packed fp16x2 {0,+-1.0}; 4 lat-4 ALU ops.
__device__ __forceinline__ uint32_t tern2h(uint32_t w0, uint32_t w1) {
    uint32_t p = __byte_perm(w0, w1, 0x5410);
    uint32_t m = (p & 0x00010001u) * 0x3C00u;
    return m | (p & 0x80008000u);
}

__device__ __forceinline__ void mma16816(float d[4],
                                         uint32_t a0, uint32_t a1, uint32_t a2, uint32_t a3,
                                         uint32_t b0, uint32_t b1) {
    asm volatile(
        "mma.sync.aligned.m16n8k16.row.col.f32.f16.f16.f32 "
        "{%0,%1,%2,%3}, {%4,%5,%6,%7}, {%8,%9}, {%0,%1,%2,%3};\n"
        : "+f"(d[0]), "+f"(d[1]), "+f"(d[2]), "+f"(d[3])
        : "r"(a0), "r"(a1), "r"(a2), "r"(a3), "r"(b0), "r"(b1));
}

// ---------------- main GEMM (per-split partial) ------------------------------
__global__ void __launch_bounds__(NTHREADS, 2)
lin2b_main(const float* __restrict__ X, const int* __restrict__ W)
{
    __shared__ __align__(16) unsigned char xsm[32 * XROW];   // 17 KB, read-only after init

    int tid  = threadIdx.x;
    int wid  = tid >> 5;
    int lane = tid & 31;
    int rr   = lane >> 2;
    int cc   = lane & 3;

    int mtile = blockIdx.x >> 4;
    int split = blockIdx.x & 15;
    int row0  = mtile * TM;
    int k0    = split * (CHUNKS * 64);      // first k of this CTA's slice

    // ---- prologue: convert this CTA's x slice (32 x 256) f32 -> fp16 smem ---
    {
        int xr  = tid >> 3;                 // batch row 0..31
        int kb  = (tid & 7) * 32;           // 32 k per thread
        const float* xs = X + (size_t)xr * INK + k0 + kb;
        unsigned char* xd = xsm + xr * XROW + kb * 2;
#pragma unroll
        for (int g = 0; g < 2; ++g) {       // 2 groups of 16 k -> 32B stores
            uint4 st[2];
#pragma unroll
            for (int q = 0; q < 2; ++q) {
                float4 v0 = *reinterpret_cast<const float4*>(xs + g * 16 + q * 8);
                float4 v1 = *reinterpret_cast<const float4*>(xs + g * 16 + q * 8 + 4);
                __half2 p0 = __floats2half2_rn(v0.x, v0.y);
                __half2 p1 = __floats2half2_rn(v0.z, v0.w);
                __half2 p2 = __floats2half2_rn(v1.x, v1.y);
                __half2 p3 = __floats2half2_rn(v1.z, v1.w);
                st[q].x = *reinterpret_cast<uint32_t*>(&p0);
                st[q].y = *reinterpret_cast<uint32_t*>(&p1);
                st[q].z = *reinterpret_cast<uint32_t*>(&p2);
                st[q].w = *reinterpret_cast<uint32_t*>(&p3);
            }
            *reinterpret_cast<uint4*>(xd + g * 32)      = st[0];
            *reinterpret_cast<uint4*>(xd + g * 32 + 16) = st[1];
        }
    }

    // W frag pointers: rows (wid*16+rr) and +8, cols 4*cc within each chunk
    const int* wp0 = W + (size_t)(row0 + wid * 16 + rr) * INK + k0 + 4 * cc;
    const int* wp1 = wp0 + (size_t)8 * INK;

    float acc[4][4];
#pragma unroll
    for (int i = 0; i < 4; ++i)
#pragma unroll
        for (int j = 0; j < 4; ++j) acc[i][j] = 0.0f;

    uint4 w0[8], w1[8];

    // W chunk 0 -> w0 (issue before the one-and-only barrier)
#pragma unroll
    for (int s = 0; s < 4; ++s) {
        w0[2*s]   = *reinterpret_cast<const uint4*>(wp0 + s * 16);
        w0[2*s+1] = *reinterpret_cast<const uint4*>(wp1 + s * 16);
    }
    __syncthreads();    // x smem ready; never needed again (read-only)

    const unsigned char* xb = xsm + rr * XROW + cc * 8;

#pragma unroll
    for (int c = 0; c < CHUNKS; ++c) {
        uint4* wcur = (c & 1) ? w1 : w0;
        uint4* wnxt = (c & 1) ? w0 : w1;

        if (c + 1 < CHUNKS) {
#pragma unroll
            for (int s = 0; s < 4; ++s) {
                wnxt[2*s]   = *reinterpret_cast<const uint4*>(wp0 + (c + 1) * 64 + s * 16);
                wnxt[2*s+1] = *reinterpret_cast<const uint4*>(wp1 + (c + 1) * 64 + s * 16);
            }
        }

#pragma unroll
        for (int s = 0; s < 4; ++s) {
            uint4 wa = wcur[2*s];
            uint4 wb = wcur[2*s+1];
            uint32_t a0 = tern2h(wa.x, wa.y);
            uint32_t a2 = tern2h(wa.z, wa.w);
            uint32_t a1 = tern2h(wb.x, wb.y);
            uint32_t a3 = tern2h(wb.z, wb.w);
#pragma unroll
            for (int nf = 0; nf < 4; ++nf) {
                uint2 bv = *reinterpret_cast<const uint2*>(
                    xb + nf * (8 * XROW) + c * 128 + s * 32);
                mma16816(acc[nf], a0, a1, a2, a3, bv.x, bv.y);
            }
        }
    }

    // ---- partial epilogue (scale/bias applied in reduce) ----
    int o0 = row0 + wid * 16 + rr;
    int o1 = o0 + 8;
    float* pb = g_part + (size_t)split * 32 * OUTN;
#pragma unroll
    for (int nf = 0; nf < 4; ++nf) {
        int b0 = nf * 8 + 2 * cc;
        int b1 = b0 + 1;
        pb[(size_t)b0 * OUTN + o0] = acc[nf][0];
        pb[(size_t)b1 * OUTN + o0] = acc[nf][1];
        pb[(size_t)b0 * OUTN + o1] = acc[nf][2];
        pb[(size_t)b1 * OUTN + o1] = acc[nf][3];
    }
}

// ---------------- reduce: out = bias + scale * sum(parts), vectorized x4 -----
__global__ void __launch_bounds__(256)
reduce_k(const float* __restrict__ SC, const float* __restrict__ BI,
         float* __restrict__ OUT)
{
    int t = blockIdx.x * blockDim.x + threadIdx.x;
    if (t >= 32 * OUTN / 4) return;
    size_t idx = (size_t)t * 4;
    int o = (int)(idx % OUTN);

    float4 s = *reinterpret_cast<const float4*>(g_part + idx);
#pragma unroll
    for (int sp = 1; sp < NSPLIT; ++sp) {
        float4 p = *reinterpret_cast<const float4*>(g_part + (size_t)sp * 32 * OUTN + idx);
        s.x += p.x; s.y += p.y; s.z += p.z; s.w += p.w;
    }
    float4 sc = *reinterpret_cast<const float4*>(SC + o);
    float4 bi = *reinterpret_cast<const float4*>(BI + o);
    float4 r;
    r.x = fmaf(sc.x, s.x, bi.x);
    r.y = fmaf(sc.y, s.y, bi.y);
    r.z = fmaf(sc.z, s.z, bi.z);
    r.w = fmaf(sc.w, s.w, bi.w);
    *reinterpret_cast<float4*>(OUT + idx) = r;
}

extern "C" void kernel_launch(void* const* d_in, const int* in_sizes, int n_in,
                              void* d_out, int out_size) {
    (void)in_sizes; (void)n_in; (void)out_size;
    const float* x  = (const float*)d_in[0];
    const int*   wq = (const int*)d_in[1];
    const float* sc = (const float*)d_in[2];
    const float* bi = (const float*)d_in[3];
    float* out = (float*)d_out;

    lin2b_main<<<NCTA, NTHREADS>>>(x, wq);
    reduce_k<<<(32 * OUTN / 4 + 255) / 256, 256>>>(sc, bi, out);
}